// round 5
// baseline (speedup 1.0000x reference)
#include <cuda_runtime.h>
#include <cuda_bf16.h>
#include <cstdint>
#include <cstddef>

// Problem constants
#define T_SEQ 2048
#define DM    1024
#define C3    3072
#define NH    16
#define HD    64
#define KK3   3072   // split-expanded K (3 x 1024)

// ---------------------------------------------------------------------------
// Scratch (device globals: allocation-free per harness rules)
// ---------------------------------------------------------------------------
__device__ float g_qkv[(size_t)4096 * 3072];             // [B*T, 3C] fp32
__device__ float g_att[(size_t)4096 * 1024];             // [B*T, C]  fp32
__device__ __nv_bfloat16 g_abuf[(size_t)4096 * KK3];     // x split    [Ah|Al|Ah]
__device__ __nv_bfloat16 g_tbuf[(size_t)4096 * KK3];     // attn split [Ah|Al|Ah]
__device__ __nv_bfloat16 g_wq[(size_t)3072 * KK3];       // w_qkv^T    [Bh|Bh|Bl]
__device__ __nv_bfloat16 g_wp[(size_t)1024 * KK3];       // w_proj^T   [Bh|Bh|Bl]

// ---------------------------------------------------------------------------
// mma.sync / ldmatrix / cp.async helpers (plain sm_103-compatible PTX)
// ---------------------------------------------------------------------------
__device__ __forceinline__ uint32_t cvta_s(const void* p) {
    return (uint32_t)__cvta_generic_to_shared(p);
}
__device__ __forceinline__ void cp_async16(uint32_t saddr, const void* g) {
    asm volatile("cp.async.cg.shared.global [%0], [%1], 16;"
                 :: "r"(saddr), "l"(g) : "memory");
}
__device__ __forceinline__ void ldmx4(uint32_t* r, uint32_t addr) {
    asm volatile("ldmatrix.sync.aligned.m8n8.x4.shared.b16 {%0,%1,%2,%3}, [%4];"
                 : "=r"(r[0]), "=r"(r[1]), "=r"(r[2]), "=r"(r[3]) : "r"(addr));
}
__device__ __forceinline__ void mma16816(float* c, const uint32_t* a,
                                         uint32_t b0, uint32_t b1) {
    asm volatile(
        "mma.sync.aligned.m16n8k16.row.col.f32.bf16.bf16.f32 "
        "{%0,%1,%2,%3}, {%4,%5,%6,%7}, {%8,%9}, {%0,%1,%2,%3};"
        : "+f"(c[0]), "+f"(c[1]), "+f"(c[2]), "+f"(c[3])
        : "r"(a[0]), "r"(a[1]), "r"(a[2]), "r"(a[3]), "r"(b0), "r"(b1));
}

// ---------------------------------------------------------------------------
// Conversion kernels
// ---------------------------------------------------------------------------
// fp32 [4096,1024] -> A' bf16 [4096,3072] = [hi | lo | hi]
__global__ __launch_bounds__(256) void split_a_kernel(
    const float* __restrict__ in, __nv_bfloat16* __restrict__ out)
{
    int idx = blockIdx.x * 256 + threadIdx.x;      // 4096 rows x 256 vec4
    int row = idx >> 8;
    int c   = (idx & 255) << 2;
    float4 v = *(const float4*)(in + (size_t)row * 1024 + c);
    float vv[4] = {v.x, v.y, v.z, v.w};
    __nv_bfloat16 h[4], l[4];
#pragma unroll
    for (int j = 0; j < 4; j++) {
        h[j] = __float2bfloat16(vv[j]);
        l[j] = __float2bfloat16(vv[j] - __bfloat162float(h[j]));
    }
    __nv_bfloat162 h01(h[0], h[1]), h23(h[2], h[3]);
    __nv_bfloat162 l01(l[0], l[1]), l23(l[2], l[3]);
    size_t base = (size_t)row * KK3;
    *(__nv_bfloat162*)(out + base + c)            = h01;
    *(__nv_bfloat162*)(out + base + c + 2)        = h23;
    *(__nv_bfloat162*)(out + base + 1024 + c)     = l01;
    *(__nv_bfloat162*)(out + base + 1024 + c + 2) = l23;
    *(__nv_bfloat162*)(out + base + 2048 + c)     = h01;
    *(__nv_bfloat162*)(out + base + 2048 + c + 2) = h23;
}

// w [1024, N] fp32 -> B' bf16 [N, 3072] = [hi | hi | lo]  (transpose + split)
__global__ __launch_bounds__(256) void tsplit_kernel(
    const float* __restrict__ w, __nv_bfloat16* __restrict__ out, int N)
{
    __shared__ float t[32][33];                    // t[k_local][n_local]
    const int n0 = blockIdx.x << 5;
    const int k0 = blockIdx.y << 5;
    const int tx = threadIdx.x & 31;
    const int ty = threadIdx.x >> 5;               // 0..7
#pragma unroll
    for (int i = 0; i < 4; i++)
        t[ty + 8 * i][tx] = w[(size_t)(k0 + ty + 8 * i) * N + n0 + tx];
    __syncthreads();
#pragma unroll
    for (int i = 0; i < 4; i++) {
        int r = ty + 8 * i;                        // local n
        float v = t[tx][r];                        // = w[k0+tx][n0+r]
        __nv_bfloat16 h = __float2bfloat16(v);
        __nv_bfloat16 l = __float2bfloat16(v - __bfloat162float(h));
        size_t o = (size_t)(n0 + r) * KK3 + k0 + tx;
        out[o]        = h;
        out[o + 1024] = h;
        out[o + 2048] = l;
    }
}

// ---------------------------------------------------------------------------
// bf16 tensor-core GEMM via mma.sync: C[M,N] = A'[M,3072] @ B'[N,3072]^T + bias
// 128x128 tile, BK=32, 8 warps (4x2), cp.async double buffer, pad-40 SMEM.
// ---------------------------------------------------------------------------
#define ASTR 40   // smem row stride (elements) — conflict-free for ldmatrix

__device__ __forceinline__ void stage_load(
    __nv_bfloat16* As, __nv_bfloat16* Bs,
    const __nv_bfloat16* Ag, const __nv_bfloat16* Bg,
    int r0, int c0, int kb)
{
#pragma unroll
    for (int j = 0; j < 2; j++) {
        int r = r0 + (j << 6);
        cp_async16(cvta_s(As + r * ASTR + c0), Ag + (size_t)r * KK3 + kb + c0);
        cp_async16(cvta_s(Bs + r * ASTR + c0), Bg + (size_t)r * KK3 + kb + c0);
    }
    asm volatile("cp.async.commit_group;" ::: "memory");
}

__global__ __launch_bounds__(256) void gemm_mma_kernel(
    const __nv_bfloat16* __restrict__ A, const __nv_bfloat16* __restrict__ B,
    const float* __restrict__ bias, float* __restrict__ C, int M, int N)
{
    __shared__ __nv_bfloat16 Asm[2][128 * ASTR];
    __shared__ __nv_bfloat16 Bsm[2][128 * ASTR];

    const int tid  = threadIdx.x;
    const int lane = tid & 31;
    const int wid  = tid >> 5;
    const int wm   = wid & 3;          // 4 warps along M (32 rows each)
    const int wn   = wid >> 2;         // 2 warps along N (64 cols each)
    const int m0   = (int)blockIdx.y << 7;
    const int n0   = (int)blockIdx.x << 7;

    float acc[2][8][4];
#pragma unroll
    for (int i = 0; i < 2; i++)
#pragma unroll
        for (int j = 0; j < 8; j++)
#pragma unroll
            for (int k = 0; k < 4; k++) acc[i][j][k] = 0.f;

    const __nv_bfloat16* Ag = A + (size_t)m0 * KK3;
    const __nv_bfloat16* Bg = B + (size_t)n0 * KK3;

    const int r0 = tid >> 2;           // 0..63 (x2 passes -> 128 rows)
    const int c0 = (tid & 3) << 3;     // 0,8,16,24

    const int nk = KK3 >> 5;           // 96
    stage_load(Asm[0], Bsm[0], Ag, Bg, r0, c0, 0);
    stage_load(Asm[1], Bsm[1], Ag, Bg, r0, c0, 32);

    // ldmatrix source coordinates
    const int arow  = wm * 32 + (lane & 15);
    const int acsel = (lane >> 4) << 3;
    const int brow  = wn * 64 + (lane & 7) + ((lane >> 4) << 3);
    const int bksel = ((lane >> 3) & 1) << 3;

    for (int kt = 0; kt < nk; kt++) {
        if (kt + 1 < nk) asm volatile("cp.async.wait_group 1;" ::: "memory");
        else             asm volatile("cp.async.wait_group 0;" ::: "memory");
        __syncthreads();
        const int s = kt & 1;

#pragma unroll
        for (int ks = 0; ks < 32; ks += 16) {
            uint32_t af[2][4];
#pragma unroll
            for (int am = 0; am < 2; am++)
                ldmx4(af[am], cvta_s(&Asm[s][(arow + am * 16) * ASTR + ks + acsel]));
#pragma unroll
            for (int bn = 0; bn < 4; bn++) {
                uint32_t bf[4];
                ldmx4(bf, cvta_s(&Bsm[s][(brow + bn * 16) * ASTR + ks + bksel]));
#pragma unroll
                for (int am = 0; am < 2; am++) {
                    mma16816(acc[am][2 * bn],     af[am], bf[0], bf[1]);
                    mma16816(acc[am][2 * bn + 1], af[am], bf[2], bf[3]);
                }
            }
        }
        __syncthreads();
        if (kt + 2 < nk)
            stage_load(Asm[s], Bsm[s], Ag, Bg, r0, c0, (kt + 2) << 5);
    }

    // epilogue: bias add + store (float2 per atom-row)
    const int trow = lane >> 2;
    const int tcol = (lane & 3) << 1;
#pragma unroll
    for (int am = 0; am < 2; am++) {
#pragma unroll
        for (int bn = 0; bn < 8; bn++) {
            int col = n0 + wn * 64 + bn * 8 + tcol;
            float2 bv = *(const float2*)(bias + col);
            int rg = m0 + wm * 32 + am * 16 + trow;
            float2 o0, o1;
            o0.x = acc[am][bn][0] + bv.x; o0.y = acc[am][bn][1] + bv.y;
            o1.x = acc[am][bn][2] + bv.x; o1.y = acc[am][bn][3] + bv.y;
            *(float2*)(C + (size_t)rg * N + col)       = o0;
            *(float2*)(C + (size_t)(rg + 8) * N + col) = o1;
        }
    }
}

// ---------------------------------------------------------------------------
// Flash attention (fp32, causal). One block = 64 queries of one (b,h).
// ---------------------------------------------------------------------------
__global__ __launch_bounds__(256) void attn_kernel(
    const float* __restrict__ qkv, float* __restrict__ outa)
{
    extern __shared__ float sm[];
    float (*Qt)[68] = (float(*)[68])(sm);          // Qt[d][m]
    float (*Kt)[68] = (float(*)[68])(sm + 4352);   // Kt[d][s]
    float (*Vs)[68] = (float(*)[68])(sm + 8704);   // Vs[s][d]
    float (*Ps)[68] = (float(*)[68])(sm + 13056);  // Ps[m][s]

    const int bh = blockIdx.y;
    const int b  = bh >> 4;
    const int h  = bh & 15;
    const int m0 = blockIdx.x << 6;
    const int tid = threadIdx.x;
    const int tx  = tid & 15;
    const int ty  = tid >> 4;

    const float* qb = qkv + ((size_t)(b * T_SEQ + m0)) * C3 + h * HD;
    for (int i = tid; i < 1024; i += 256) {
        int r = i >> 4, d4 = (i & 15) << 2;
        float4 v = *(const float4*)(qb + (size_t)r * C3 + d4);
        Qt[d4 + 0][r] = v.x; Qt[d4 + 1][r] = v.y;
        Qt[d4 + 2][r] = v.z; Qt[d4 + 3][r] = v.w;
    }

    float mr[4], lr[4], acc[4][4];
#pragma unroll
    for (int i = 0; i < 4; i++) {
        mr[i] = -1e30f; lr[i] = 0.f;
#pragma unroll
        for (int j = 0; j < 4; j++) acc[i][j] = 0.f;
    }

    const int nkb = (m0 >> 6) + 1;
    for (int kb = 0; kb < nkb; kb++) {
        const int n0 = kb << 6;
        const float* kp = qkv + ((size_t)(b * T_SEQ + n0)) * C3 + DM + h * HD;
        const float* vp = kp + DM;

        __syncthreads();
        for (int i = tid; i < 1024; i += 256) {
            int r = i >> 4, d4 = (i & 15) << 2;
            float4 kv = *(const float4*)(kp + (size_t)r * C3 + d4);
            Kt[d4 + 0][r] = kv.x; Kt[d4 + 1][r] = kv.y;
            Kt[d4 + 2][r] = kv.z; Kt[d4 + 3][r] = kv.w;
            *(float4*)&Vs[r][d4] = *(const float4*)(vp + (size_t)r * C3 + d4);
        }
        __syncthreads();

        float s[4][4];
#pragma unroll
        for (int i = 0; i < 4; i++)
#pragma unroll
            for (int j = 0; j < 4; j++) s[i][j] = 0.f;

#pragma unroll 8
        for (int d = 0; d < 64; d++) {
            float4 qa = *(const float4*)&Qt[d][ty << 2];
            float4 ka = *(const float4*)&Kt[d][tx << 2];
            float a[4]  = {qa.x, qa.y, qa.z, qa.w};
            float bb[4] = {ka.x, ka.y, ka.z, ka.w};
#pragma unroll
            for (int i = 0; i < 4; i++)
#pragma unroll
                for (int j = 0; j < 4; j++)
                    s[i][j] = fmaf(a[i], bb[j], s[i][j]);
        }

        const bool diag = (n0 == m0);
#pragma unroll
        for (int i = 0; i < 4; i++) {
            int row = (ty << 2) + i;
#pragma unroll
            for (int j = 0; j < 4; j++) {
                int col = (tx << 2) + j;
                float sv = s[i][j] * 0.125f;
                if (diag && col > row) sv = -1e30f;
                s[i][j] = sv;
            }
        }

#pragma unroll
        for (int i = 0; i < 4; i++) {
            float mx = fmaxf(fmaxf(s[i][0], s[i][1]), fmaxf(s[i][2], s[i][3]));
#pragma unroll
            for (int off = 8; off > 0; off >>= 1)
                mx = fmaxf(mx, __shfl_xor_sync(0xffffffffu, mx, off, 16));
            float mnew = fmaxf(mr[i], mx);
            float corr = __expf(mr[i] - mnew);
            float ls = 0.f;
#pragma unroll
            for (int j = 0; j < 4; j++) {
                s[i][j] = __expf(s[i][j] - mnew);
                ls += s[i][j];
            }
#pragma unroll
            for (int off = 8; off > 0; off >>= 1)
                ls += __shfl_xor_sync(0xffffffffu, ls, off, 16);
            lr[i] = lr[i] * corr + ls;
            mr[i] = mnew;
#pragma unroll
            for (int j = 0; j < 4; j++) acc[i][j] *= corr;
        }

#pragma unroll
        for (int i = 0; i < 4; i++)
#pragma unroll
            for (int j = 0; j < 4; j++)
                Ps[(ty << 2) + i][(tx << 2) + j] = s[i][j];
        __syncthreads();

#pragma unroll 8
        for (int ss = 0; ss < 64; ss++) {
            float4 vv = *(const float4*)&Vs[ss][tx << 2];
            float vj[4] = {vv.x, vv.y, vv.z, vv.w};
            float p[4];
#pragma unroll
            for (int i = 0; i < 4; i++) p[i] = Ps[(ty << 2) + i][ss];
#pragma unroll
            for (int i = 0; i < 4; i++)
#pragma unroll
                for (int j = 0; j < 4; j++)
                    acc[i][j] = fmaf(p[i], vj[j], acc[i][j]);
        }
    }

#pragma unroll
    for (int i = 0; i < 4; i++) {
        int row = m0 + (ty << 2) + i;
        float inv = 1.f / lr[i];
        float4 o;
        o.x = acc[i][0] * inv; o.y = acc[i][1] * inv;
        o.z = acc[i][2] * inv; o.w = acc[i][3] * inv;
        *(float4*)(outa + ((size_t)(b * T_SEQ) + row) * DM + h * HD + (tx << 2)) = o;
    }
}

// ---------------------------------------------------------------------------
extern "C" void kernel_launch(void* const* d_in, const int* in_sizes, int n_in,
                              void* d_out, int out_size)
{
    const float* x      = (const float*)d_in[0];
    const float* w_qkv  = (const float*)d_in[1];
    const float* b_qkv  = (const float*)d_in[2];
    const float* w_proj = (const float*)d_in[3];
    const float* b_proj = (const float*)d_in[4];
    float* out = (float*)d_out;

    float* qkv_buf = nullptr; float* att_buf = nullptr;
    __nv_bfloat16 *abuf, *tbuf, *wq, *wp;
    cudaGetSymbolAddress((void**)&qkv_buf, g_qkv);
    cudaGetSymbolAddress((void**)&att_buf, g_att);
    cudaGetSymbolAddress((void**)&abuf, g_abuf);
    cudaGetSymbolAddress((void**)&tbuf, g_tbuf);
    cudaGetSymbolAddress((void**)&wq, g_wq);
    cudaGetSymbolAddress((void**)&wp, g_wp);

    const int smem_attn = 4 * 64 * 68 * (int)sizeof(float);  // 69632 B
    cudaFuncSetAttribute(attn_kernel,
                         cudaFuncAttributeMaxDynamicSharedMemorySize, smem_attn);

    // 1) split x -> A' [4096,3072]
    split_a_kernel<<<4096, 256>>>(x, abuf);
    // 2) transpose+split w_qkv -> B' [3072,3072]
    tsplit_kernel<<<dim3(96, 32), 256>>>(w_qkv, wq, 3072);
    // 3) QKV GEMM (tensor cores): grid (N/128, M/128)
    gemm_mma_kernel<<<dim3(24, 32), 256>>>(abuf, wq, b_qkv, qkv_buf, 4096, 3072);
    // 4) causal flash attention
    attn_kernel<<<dim3(T_SEQ / 64, 2 * NH), 256, smem_attn>>>(qkv_buf, att_buf);
    // 5) split attention output -> A' layout
    split_a_kernel<<<4096, 256>>>(att_buf, tbuf);
    // 6) transpose+split w_proj -> B' [1024,3072]
    tsplit_kernel<<<dim3(32, 32), 256>>>(w_proj, wp, 1024);
    // 7) proj GEMM (tensor cores)
    gemm_mma_kernel<<<dim3(8, 32), 256>>>(tbuf, wp, b_proj, out, 4096, 1024);
}

// round 8
// speedup vs baseline: 3.0305x; 3.0305x over previous
#include <cuda_runtime.h>
#include <cuda_bf16.h>
#include <cuda_fp16.h>
#include <cstdint>
#include <cstddef>

// Problem constants
#define T_SEQ 2048
#define DM    1024
#define C3    3072
#define NH    16
#define HD    64
#define KK3   3072   // split-expanded K (3 x 1024)

// ---------------------------------------------------------------------------
// Scratch (device globals: allocation-free per harness rules)
// ---------------------------------------------------------------------------
__device__ float g_qkv[(size_t)4096 * 3072];             // [B*T, 3C] fp32
__device__ float g_att[(size_t)4096 * 1024];             // [B*T, C]  fp32
__device__ __nv_bfloat16 g_abuf[(size_t)4096 * KK3];     // x split    [Ah|Al|Ah]
__device__ __nv_bfloat16 g_tbuf[(size_t)4096 * KK3];     // attn split [Ah|Al|Ah]
__device__ __nv_bfloat16 g_wq[(size_t)3072 * KK3];       // w_qkv^T    [Bh|Bh|Bl]
__device__ __nv_bfloat16 g_wp[(size_t)1024 * KK3];       // w_proj^T   [Bh|Bh|Bl]

// ---------------------------------------------------------------------------
// mma.sync / ldmatrix / cp.async helpers (plain sm_103-compatible PTX)
// ---------------------------------------------------------------------------
__device__ __forceinline__ uint32_t cvta_s(const void* p) {
    return (uint32_t)__cvta_generic_to_shared(p);
}
__device__ __forceinline__ void cp_async16(uint32_t saddr, const void* g) {
    asm volatile("cp.async.cg.shared.global [%0], [%1], 16;"
                 :: "r"(saddr), "l"(g) : "memory");
}
__device__ __forceinline__ void ldmx4(uint32_t* r, uint32_t addr) {
    asm volatile("ldmatrix.sync.aligned.m8n8.x4.shared.b16 {%0,%1,%2,%3}, [%4];"
                 : "=r"(r[0]), "=r"(r[1]), "=r"(r[2]), "=r"(r[3]) : "r"(addr));
}
__device__ __forceinline__ void ldmx4_trans(uint32_t* r, uint32_t addr) {
    asm volatile("ldmatrix.sync.aligned.m8n8.x4.trans.shared.b16 {%0,%1,%2,%3}, [%4];"
                 : "=r"(r[0]), "=r"(r[1]), "=r"(r[2]), "=r"(r[3]) : "r"(addr));
}
__device__ __forceinline__ void mma_bf16(float* c, const uint32_t* a,
                                         uint32_t b0, uint32_t b1) {
    asm volatile(
        "mma.sync.aligned.m16n8k16.row.col.f32.bf16.bf16.f32 "
        "{%0,%1,%2,%3}, {%4,%5,%6,%7}, {%8,%9}, {%0,%1,%2,%3};"
        : "+f"(c[0]), "+f"(c[1]), "+f"(c[2]), "+f"(c[3])
        : "r"(a[0]), "r"(a[1]), "r"(a[2]), "r"(a[3]), "r"(b0), "r"(b1));
}
__device__ __forceinline__ void mma_f16(float* c, const uint32_t* a,
                                        uint32_t b0, uint32_t b1) {
    asm volatile(
        "mma.sync.aligned.m16n8k16.row.col.f32.f16.f16.f32 "
        "{%0,%1,%2,%3}, {%4,%5,%6,%7}, {%8,%9}, {%0,%1,%2,%3};"
        : "+f"(c[0]), "+f"(c[1]), "+f"(c[2]), "+f"(c[3])
        : "r"(a[0]), "r"(a[1]), "r"(a[2]), "r"(a[3]), "r"(b0), "r"(b1));
}
__device__ __forceinline__ uint32_t pack_h2(float a, float b) {
    __half2 h = __floats2half2_rn(a, b);
    return *(uint32_t*)&h;
}

// ---------------------------------------------------------------------------
// Conversion kernels
// ---------------------------------------------------------------------------
// fp32 [4096,1024] -> A' bf16 [4096,3072] = [hi | lo | hi]
__global__ __launch_bounds__(256) void split_a_kernel(
    const float* __restrict__ in, __nv_bfloat16* __restrict__ out)
{
    int idx = blockIdx.x * 256 + threadIdx.x;
    int row = idx >> 8;
    int c   = (idx & 255) << 2;
    float4 v = *(const float4*)(in + (size_t)row * 1024 + c);
    float vv[4] = {v.x, v.y, v.z, v.w};
    __nv_bfloat16 h[4], l[4];
#pragma unroll
    for (int j = 0; j < 4; j++) {
        h[j] = __float2bfloat16(vv[j]);
        l[j] = __float2bfloat16(vv[j] - __bfloat162float(h[j]));
    }
    __nv_bfloat162 h01(h[0], h[1]), h23(h[2], h[3]);
    __nv_bfloat162 l01(l[0], l[1]), l23(l[2], l[3]);
    size_t base = (size_t)row * KK3;
    *(__nv_bfloat162*)(out + base + c)            = h01;
    *(__nv_bfloat162*)(out + base + c + 2)        = h23;
    *(__nv_bfloat162*)(out + base + 1024 + c)     = l01;
    *(__nv_bfloat162*)(out + base + 1024 + c + 2) = l23;
    *(__nv_bfloat162*)(out + base + 2048 + c)     = h01;
    *(__nv_bfloat162*)(out + base + 2048 + c + 2) = h23;
}

// w [1024, N] fp32 -> B' bf16 [N, 3072] = [hi | hi | lo]
__global__ __launch_bounds__(256) void tsplit_kernel(
    const float* __restrict__ w, __nv_bfloat16* __restrict__ out, int N)
{
    __shared__ float t[32][33];
    const int n0 = blockIdx.x << 5;
    const int k0 = blockIdx.y << 5;
    const int tx = threadIdx.x & 31;
    const int ty = threadIdx.x >> 5;
#pragma unroll
    for (int i = 0; i < 4; i++)
        t[ty + 8 * i][tx] = w[(size_t)(k0 + ty + 8 * i) * N + n0 + tx];
    __syncthreads();
#pragma unroll
    for (int i = 0; i < 4; i++) {
        int r = ty + 8 * i;
        float v = t[tx][r];
        __nv_bfloat16 h = __float2bfloat16(v);
        __nv_bfloat16 l = __float2bfloat16(v - __bfloat162float(h));
        size_t o = (size_t)(n0 + r) * KK3 + k0 + tx;
        out[o]        = h;
        out[o + 1024] = h;
        out[o + 2048] = l;
    }
}

// ---------------------------------------------------------------------------
// bf16 tensor-core GEMM: C[M,N] = A'[M,3072] @ B'[N,3072]^T + bias
// 128x128 tile, BK=32, 3-stage cp.async pipeline, ONE sync per K-iter.
// ---------------------------------------------------------------------------
#define ASTR 40

__global__ __launch_bounds__(256) void gemm_mma_kernel(
    const __nv_bfloat16* __restrict__ A, const __nv_bfloat16* __restrict__ B,
    const float* __restrict__ bias, float* __restrict__ C, int M, int N)
{
    extern __shared__ __nv_bfloat16 dsm[];
    __nv_bfloat16* Asm = dsm;                    // [3][128*ASTR]
    __nv_bfloat16* Bsm = dsm + 3 * 128 * ASTR;   // [3][128*ASTR]

    const int tid  = threadIdx.x;
    const int lane = tid & 31;
    const int wid  = tid >> 5;
    const int wm   = wid & 3;
    const int wn   = wid >> 2;
    const int m0   = (int)blockIdx.y << 7;
    const int n0   = (int)blockIdx.x << 7;

    float acc[2][8][4];
#pragma unroll
    for (int i = 0; i < 2; i++)
#pragma unroll
        for (int j = 0; j < 8; j++)
#pragma unroll
            for (int k = 0; k < 4; k++) acc[i][j][k] = 0.f;

    const __nv_bfloat16* Ag = A + (size_t)m0 * KK3;
    const __nv_bfloat16* Bg = B + (size_t)n0 * KK3;

    const int r0 = tid >> 2;
    const int c0 = (tid & 3) << 3;

    auto stage_load = [&](int s, int kb) {
        __nv_bfloat16* As = Asm + s * 128 * ASTR;
        __nv_bfloat16* Bs = Bsm + s * 128 * ASTR;
#pragma unroll
        for (int j = 0; j < 2; j++) {
            int r = r0 + (j << 6);
            cp_async16(cvta_s(As + r * ASTR + c0), Ag + (size_t)r * KK3 + kb + c0);
            cp_async16(cvta_s(Bs + r * ASTR + c0), Bg + (size_t)r * KK3 + kb + c0);
        }
        asm volatile("cp.async.commit_group;" ::: "memory");
    };

    const int nk = KK3 >> 5;   // 96
    stage_load(0, 0);
    stage_load(1, 32);

    const int arow  = wm * 32 + (lane & 15);
    const int acsel = (lane >> 4) << 3;
    const int brow  = wn * 64 + (lane & 7) + ((lane >> 4) << 3);
    const int bksel = ((lane >> 3) & 1) << 3;

    for (int kt = 0; kt < nk; kt++) {
        if (kt + 1 < nk) asm volatile("cp.async.wait_group 1;" ::: "memory");
        else             asm volatile("cp.async.wait_group 0;" ::: "memory");
        __syncthreads();
        if (kt + 2 < nk) stage_load((kt + 2) % 3, (kt + 2) << 5);

        const __nv_bfloat16* As = Asm + (kt % 3) * 128 * ASTR;
        const __nv_bfloat16* Bs = Bsm + (kt % 3) * 128 * ASTR;
#pragma unroll
        for (int ks = 0; ks < 32; ks += 16) {
            uint32_t af[2][4];
#pragma unroll
            for (int am = 0; am < 2; am++)
                ldmx4(af[am], cvta_s(As + (arow + am * 16) * ASTR + ks + acsel));
#pragma unroll
            for (int bn = 0; bn < 4; bn++) {
                uint32_t bf[4];
                ldmx4(bf, cvta_s(Bs + (brow + bn * 16) * ASTR + ks + bksel));
#pragma unroll
                for (int am = 0; am < 2; am++) {
                    mma_bf16(acc[am][2 * bn],     af[am], bf[0], bf[1]);
                    mma_bf16(acc[am][2 * bn + 1], af[am], bf[2], bf[3]);
                }
            }
        }
    }

    const int trow = lane >> 2;
    const int tcol = (lane & 3) << 1;
#pragma unroll
    for (int am = 0; am < 2; am++) {
#pragma unroll
        for (int bn = 0; bn < 8; bn++) {
            int col = n0 + wn * 64 + bn * 8 + tcol;
            float2 bv = *(const float2*)(bias + col);
            int rg = m0 + wm * 32 + am * 16 + trow;
            float2 o0, o1;
            o0.x = acc[am][bn][0] + bv.x; o0.y = acc[am][bn][1] + bv.y;
            o1.x = acc[am][bn][2] + bv.x; o1.y = acc[am][bn][3] + bv.y;
            *(float2*)(C + (size_t)rg * N + col)       = o0;
            *(float2*)(C + (size_t)(rg + 8) * N + col) = o1;
        }
    }
}

// ---------------------------------------------------------------------------
// Tensor-core flash attention, single-pass fp16, fp32 accumulate.
// CTA = 128 queries of one (b,h); 8 warps x 16 rows; key blocks of 64.
// ---------------------------------------------------------------------------
#define QSTR 72

__global__ __launch_bounds__(256) void attn_mma_kernel(
    const float* __restrict__ qkv, float* __restrict__ outa)
{
    __shared__ __half Qs[128][QSTR];
    __shared__ __half Ks[64][QSTR];
    __shared__ __half Vs[64][QSTR];

    const int tid  = threadIdx.x;
    const int lane = tid & 31;
    const int wid  = tid >> 5;
    const int bh = blockIdx.y;
    const int b  = bh >> 4;
    const int h  = bh & 15;
    const int m0 = (int)blockIdx.x << 7;
    const int qrow0 = wid << 4;

    // Load Q tile (fp32 -> fp16)
    const float* qb = qkv + ((size_t)(b * T_SEQ + m0)) * C3 + h * HD;
    for (int i = tid; i < 128 * 16; i += 256) {
        int r = i >> 4, c = (i & 15) << 2;
        float4 v = *(const float4*)(qb + (size_t)r * C3 + c);
        *(__half2*)&Qs[r][c]     = __floats2half2_rn(v.x, v.y);
        *(__half2*)&Qs[r][c + 2] = __floats2half2_rn(v.z, v.w);
    }

    float m_[2] = {-1e30f, -1e30f};
    float l_[2] = {0.f, 0.f};
    float o[8][4];
#pragma unroll
    for (int j = 0; j < 8; j++)
#pragma unroll
        for (int k = 0; k < 4; k++) o[j][k] = 0.f;

    const int rA = m0 + qrow0 + (lane >> 2);
    const int rB = rA + 8;

    const int nkb = (m0 >> 6) + 2;
    for (int kb = 0; kb < nkb; kb++) {
        const int n0 = kb << 6;
        const float* kp = qkv + ((size_t)(b * T_SEQ + n0)) * C3 + DM + h * HD;
        const float* vp = kp + DM;

        __syncthreads();
        for (int i = tid; i < 64 * 16; i += 256) {
            int r = i >> 4, c = (i & 15) << 2;
            float4 kv4 = *(const float4*)(kp + (size_t)r * C3 + c);
            float4 vv4 = *(const float4*)(vp + (size_t)r * C3 + c);
            *(__half2*)&Ks[r][c]     = __floats2half2_rn(kv4.x, kv4.y);
            *(__half2*)&Ks[r][c + 2] = __floats2half2_rn(kv4.z, kv4.w);
            *(__half2*)&Vs[r][c]     = __floats2half2_rn(vv4.x, vv4.y);
            *(__half2*)&Vs[r][c + 2] = __floats2half2_rn(vv4.z, vv4.w);
        }
        __syncthreads();

        // warp-tile fully masked? (all 16 rows < n0)
        if (m0 + qrow0 + 15 < n0) continue;

        // S = Q @ K^T
        float s_[8][4];
#pragma unroll
        for (int j = 0; j < 8; j++)
#pragma unroll
            for (int k = 0; k < 4; k++) s_[j][k] = 0.f;

#pragma unroll
        for (int ks = 0; ks < 64; ks += 16) {
            uint32_t a[4];
            ldmx4(a, cvta_s(&Qs[qrow0 + (lane & 15)][ks + ((lane >> 4) << 3)]));
#pragma unroll
            for (int j = 0; j < 4; j++) {
                uint32_t bf[4];
                ldmx4(bf, cvta_s(&Ks[j * 16 + (lane & 7) + ((lane >> 4) << 3)]
                                    [ks + (((lane >> 3) & 1) << 3)]));
                mma_f16(s_[2 * j],     a, bf[0], bf[1]);
                mma_f16(s_[2 * j + 1], a, bf[2], bf[3]);
            }
        }

        // scale + causal mask
#pragma unroll
        for (int j = 0; j < 8; j++) {
            int cg = n0 + j * 8 + ((lane & 3) << 1);
            s_[j][0] = (cg     <= rA) ? s_[j][0] * 0.125f : -1e30f;
            s_[j][1] = (cg + 1 <= rA) ? s_[j][1] * 0.125f : -1e30f;
            s_[j][2] = (cg     <= rB) ? s_[j][2] * 0.125f : -1e30f;
            s_[j][3] = (cg + 1 <= rB) ? s_[j][3] * 0.125f : -1e30f;
        }

        // online softmax (rows rA, rB), quad-lane reduction
        float mxA = -1e30f, mxB = -1e30f;
#pragma unroll
        for (int j = 0; j < 8; j++) {
            mxA = fmaxf(mxA, fmaxf(s_[j][0], s_[j][1]));
            mxB = fmaxf(mxB, fmaxf(s_[j][2], s_[j][3]));
        }
        mxA = fmaxf(mxA, __shfl_xor_sync(0xffffffffu, mxA, 1));
        mxA = fmaxf(mxA, __shfl_xor_sync(0xffffffffu, mxA, 2));
        mxB = fmaxf(mxB, __shfl_xor_sync(0xffffffffu, mxB, 1));
        mxB = fmaxf(mxB, __shfl_xor_sync(0xffffffffu, mxB, 2));

        float mnA = fmaxf(m_[0], mxA), mnB = fmaxf(m_[1], mxB);
        float cA = __expf(m_[0] - mnA), cB = __expf(m_[1] - mnB);
        m_[0] = mnA; m_[1] = mnB;

        float sumA = 0.f, sumB = 0.f;
#pragma unroll
        for (int j = 0; j < 8; j++) {
            s_[j][0] = __expf(s_[j][0] - mnA);
            s_[j][1] = __expf(s_[j][1] - mnA);
            s_[j][2] = __expf(s_[j][2] - mnB);
            s_[j][3] = __expf(s_[j][3] - mnB);
            sumA += s_[j][0] + s_[j][1];
            sumB += s_[j][2] + s_[j][3];
        }
        sumA += __shfl_xor_sync(0xffffffffu, sumA, 1);
        sumA += __shfl_xor_sync(0xffffffffu, sumA, 2);
        sumB += __shfl_xor_sync(0xffffffffu, sumB, 1);
        sumB += __shfl_xor_sync(0xffffffffu, sumB, 2);
        l_[0] = l_[0] * cA + sumA;
        l_[1] = l_[1] * cB + sumB;

#pragma unroll
        for (int j = 0; j < 8; j++) {
            o[j][0] *= cA; o[j][1] *= cA;
            o[j][2] *= cB; o[j][3] *= cB;
        }

        // O += P @ V  (P from S fragments, V via ldmatrix.trans)
#pragma unroll
        for (int t = 0; t < 4; t++) {
            uint32_t aP[4];
            aP[0] = pack_h2(s_[2 * t][0],     s_[2 * t][1]);
            aP[1] = pack_h2(s_[2 * t][2],     s_[2 * t][3]);
            aP[2] = pack_h2(s_[2 * t + 1][0], s_[2 * t + 1][1]);
            aP[3] = pack_h2(s_[2 * t + 1][2], s_[2 * t + 1][3]);
#pragma unroll
            for (int jd = 0; jd < 4; jd++) {
                uint32_t bf[4];
                ldmx4_trans(bf, cvta_s(&Vs[t * 16 + (((lane >> 3) & 1) << 3) + (lane & 7)]
                                          [jd * 16 + ((lane >> 4) << 3)]));
                mma_f16(o[2 * jd],     aP, bf[0], bf[1]);
                mma_f16(o[2 * jd + 1], aP, bf[2], bf[3]);
            }
        }
    }

    // epilogue: normalize, write [B*T, 1024] at head offset
    float invA = 1.f / l_[0], invB = 1.f / l_[1];
    float* oA = outa + ((size_t)(b * T_SEQ) + rA) * DM + h * HD;
    float* oB = outa + ((size_t)(b * T_SEQ) + rB) * DM + h * HD;
#pragma unroll
    for (int j = 0; j < 8; j++) {
        int col = j * 8 + ((lane & 3) << 1);
        float2 vA = {o[j][0] * invA, o[j][1] * invA};
        float2 vB = {o[j][2] * invB, o[j][3] * invB};
        *(float2*)(oA + col) = vA;
        *(float2*)(oB + col) = vB;
    }
}

// ---------------------------------------------------------------------------
extern "C" void kernel_launch(void* const* d_in, const int* in_sizes, int n_in,
                              void* d_out, int out_size)
{
    const float* x      = (const float*)d_in[0];
    const float* w_qkv  = (const float*)d_in[1];
    const float* b_qkv  = (const float*)d_in[2];
    const float* w_proj = (const float*)d_in[3];
    const float* b_proj = (const float*)d_in[4];
    float* out = (float*)d_out;

    float* qkv_buf = nullptr; float* att_buf = nullptr;
    __nv_bfloat16 *abuf, *tbuf, *wq, *wp;
    cudaGetSymbolAddress((void**)&qkv_buf, g_qkv);
    cudaGetSymbolAddress((void**)&att_buf, g_att);
    cudaGetSymbolAddress((void**)&abuf, g_abuf);
    cudaGetSymbolAddress((void**)&tbuf, g_tbuf);
    cudaGetSymbolAddress((void**)&wq, g_wq);
    cudaGetSymbolAddress((void**)&wp, g_wp);

    const int smem_gemm = 3 * 2 * 128 * ASTR * (int)sizeof(__nv_bfloat16); // 61440
    cudaFuncSetAttribute(gemm_mma_kernel,
                         cudaFuncAttributeMaxDynamicSharedMemorySize, smem_gemm);

    // 1) split x -> A' [4096,3072]
    split_a_kernel<<<4096, 256>>>(x, abuf);
    // 2) transpose+split w_qkv -> B' [3072,3072]
    tsplit_kernel<<<dim3(96, 32), 256>>>(w_qkv, wq, 3072);
    // 3) QKV GEMM (tensor cores)
    gemm_mma_kernel<<<dim3(24, 32), 256, smem_gemm>>>(abuf, wq, b_qkv, qkv_buf,
                                                      4096, 3072);
    // 4) causal flash attention (fp16 tensor cores)
    attn_mma_kernel<<<dim3(T_SEQ / 128, 2 * NH), 256>>>(qkv_buf, att_buf);
    // 5) split attention output
    split_a_kernel<<<4096, 256>>>(att_buf, tbuf);
    // 6) transpose+split w_proj -> B' [1024,3072]
    tsplit_kernel<<<dim3(32, 32), 256>>>(w_proj, wp, 1024);
    // 7) proj GEMM (tensor cores)
    gemm_mma_kernel<<<dim3(8, 32), 256, smem_gemm>>>(tbuf, wp, b_proj, out,
                                                     4096, 1024);
}

// round 9
// speedup vs baseline: 7.3088x; 2.4117x over previous
#include <cuda_runtime.h>
#include <cuda_fp16.h>
#include <cstdint>
#include <cstddef>

// Problem constants
#define T_SEQ 2048
#define DM    1024
#define C3    3072
#define NH    16
#define HD    64
#define KK    1024

// ---------------------------------------------------------------------------
// Scratch (device globals: allocation-free per harness rules)
// ---------------------------------------------------------------------------
__device__ __half g_xh[(size_t)4096 * 1024];    // x fp16
__device__ __half g_qkvh[(size_t)4096 * 3072];  // qkv fp16 [B*T, 3C]
__device__ __half g_atth[(size_t)4096 * 1024];  // attn out fp16
__device__ __half g_wqh[(size_t)3072 * 1024];   // w_qkv^T fp16 [N,K]
__device__ __half g_wph[(size_t)1024 * 1024];   // w_proj^T fp16 [N,K]

// ---------------------------------------------------------------------------
// mma.sync / ldmatrix / cp.async helpers (plain sm_103-compatible PTX)
// ---------------------------------------------------------------------------
__device__ __forceinline__ uint32_t cvta_s(const void* p) {
    return (uint32_t)__cvta_generic_to_shared(p);
}
__device__ __forceinline__ void cp_async16(uint32_t saddr, const void* g) {
    asm volatile("cp.async.cg.shared.global [%0], [%1], 16;"
                 :: "r"(saddr), "l"(g) : "memory");
}
__device__ __forceinline__ void ldmx4(uint32_t* r, uint32_t addr) {
    asm volatile("ldmatrix.sync.aligned.m8n8.x4.shared.b16 {%0,%1,%2,%3}, [%4];"
                 : "=r"(r[0]), "=r"(r[1]), "=r"(r[2]), "=r"(r[3]) : "r"(addr));
}
__device__ __forceinline__ void ldmx4_trans(uint32_t* r, uint32_t addr) {
    asm volatile("ldmatrix.sync.aligned.m8n8.x4.trans.shared.b16 {%0,%1,%2,%3}, [%4];"
                 : "=r"(r[0]), "=r"(r[1]), "=r"(r[2]), "=r"(r[3]) : "r"(addr));
}
__device__ __forceinline__ void mma_f16(float* c, const uint32_t* a,
                                        uint32_t b0, uint32_t b1) {
    asm volatile(
        "mma.sync.aligned.m16n8k16.row.col.f32.f16.f16.f32 "
        "{%0,%1,%2,%3}, {%4,%5,%6,%7}, {%8,%9}, {%0,%1,%2,%3};"
        : "+f"(c[0]), "+f"(c[1]), "+f"(c[2]), "+f"(c[3])
        : "r"(a[0]), "r"(a[1]), "r"(a[2]), "r"(a[3]), "r"(b0), "r"(b1));
}
__device__ __forceinline__ uint32_t pack_h2(float a, float b) {
    __half2 h = __floats2half2_rn(a, b);
    return *(uint32_t*)&h;
}

// ---------------------------------------------------------------------------
// Conversion kernels
// ---------------------------------------------------------------------------
// fp32 -> fp16 elementwise (vec4)
__global__ __launch_bounds__(256) void convh_kernel(
    const float* __restrict__ in, __half* __restrict__ out)
{
    int i = blockIdx.x * 256 + threadIdx.x;
    float4 v = ((const float4*)in)[i];
    ((__half2*)out)[2 * i + 0] = __floats2half2_rn(v.x, v.y);
    ((__half2*)out)[2 * i + 1] = __floats2half2_rn(v.z, v.w);
}

// w [1024, N] fp32 -> wT [N, 1024] fp16 (transpose + convert)
__global__ __launch_bounds__(256) void tconvh_kernel(
    const float* __restrict__ w, __half* __restrict__ out, int N)
{
    __shared__ float t[32][33];
    const int n0 = blockIdx.x << 5;
    const int k0 = blockIdx.y << 5;
    const int tx = threadIdx.x & 31;
    const int ty = threadIdx.x >> 5;
#pragma unroll
    for (int i = 0; i < 4; i++)
        t[ty + 8 * i][tx] = w[(size_t)(k0 + ty + 8 * i) * N + n0 + tx];
    __syncthreads();
#pragma unroll
    for (int i = 0; i < 4; i++) {
        int r = ty + 8 * i;
        out[(size_t)(n0 + r) * KK + k0 + tx] = __float2half(t[tx][r]);
    }
}

// ---------------------------------------------------------------------------
// fp16 tensor-core GEMM: C[M,N] = A[M,1024] @ B[N,1024]^T + bias
// 128x128 tile, BK=32, 3-stage cp.async pipeline, one sync per K-iter.
// HALF_OUT: write fp16 to Ch; else fp32 to Cf.
// ---------------------------------------------------------------------------
#define ASTR 40

template <bool HALF_OUT>
__global__ __launch_bounds__(256) void gemm_mma_kernel(
    const __half* __restrict__ A, const __half* __restrict__ B,
    const float* __restrict__ bias, float* __restrict__ Cf,
    __half* __restrict__ Ch, int M, int N)
{
    extern __shared__ __half dsm[];
    __half* Asm = dsm;
    __half* Bsm = dsm + 3 * 128 * ASTR;

    const int tid  = threadIdx.x;
    const int lane = tid & 31;
    const int wid  = tid >> 5;
    const int wm   = wid & 3;
    const int wn   = wid >> 2;
    const int m0   = (int)blockIdx.y << 7;
    const int n0   = (int)blockIdx.x << 7;

    float acc[2][8][4];
#pragma unroll
    for (int i = 0; i < 2; i++)
#pragma unroll
        for (int j = 0; j < 8; j++)
#pragma unroll
            for (int k = 0; k < 4; k++) acc[i][j][k] = 0.f;

    const __half* Ag = A + (size_t)m0 * KK;
    const __half* Bg = B + (size_t)n0 * KK;

    const int r0 = tid >> 2;
    const int c0 = (tid & 3) << 3;

    auto stage_load = [&](int s, int kb) {
        __half* As = Asm + s * 128 * ASTR;
        __half* Bs = Bsm + s * 128 * ASTR;
#pragma unroll
        for (int j = 0; j < 2; j++) {
            int r = r0 + (j << 6);
            cp_async16(cvta_s(As + r * ASTR + c0), Ag + (size_t)r * KK + kb + c0);
            cp_async16(cvta_s(Bs + r * ASTR + c0), Bg + (size_t)r * KK + kb + c0);
        }
        asm volatile("cp.async.commit_group;" ::: "memory");
    };

    const int nk = KK >> 5;   // 32
    stage_load(0, 0);
    stage_load(1, 32);

    const int arow  = wm * 32 + (lane & 15);
    const int acsel = (lane >> 4) << 3;
    const int brow  = wn * 64 + (lane & 7) + ((lane >> 4) << 3);
    const int bksel = ((lane >> 3) & 1) << 3;

    for (int kt = 0; kt < nk; kt++) {
        if (kt + 1 < nk) asm volatile("cp.async.wait_group 1;" ::: "memory");
        else             asm volatile("cp.async.wait_group 0;" ::: "memory");
        __syncthreads();
        if (kt + 2 < nk) stage_load((kt + 2) % 3, (kt + 2) << 5);

        const __half* As = Asm + (kt % 3) * 128 * ASTR;
        const __half* Bs = Bsm + (kt % 3) * 128 * ASTR;
#pragma unroll
        for (int ks = 0; ks < 32; ks += 16) {
            uint32_t af[2][4];
#pragma unroll
            for (int am = 0; am < 2; am++)
                ldmx4(af[am], cvta_s(As + (arow + am * 16) * ASTR + ks + acsel));
#pragma unroll
            for (int bn = 0; bn < 4; bn++) {
                uint32_t bf[4];
                ldmx4(bf, cvta_s(Bs + (brow + bn * 16) * ASTR + ks + bksel));
#pragma unroll
                for (int am = 0; am < 2; am++) {
                    mma_f16(acc[am][2 * bn],     af[am], bf[0], bf[1]);
                    mma_f16(acc[am][2 * bn + 1], af[am], bf[2], bf[3]);
                }
            }
        }
    }

    const int trow = lane >> 2;
    const int tcol = (lane & 3) << 1;
#pragma unroll
    for (int am = 0; am < 2; am++) {
#pragma unroll
        for (int bn = 0; bn < 8; bn++) {
            int col = n0 + wn * 64 + bn * 8 + tcol;
            float2 bv = *(const float2*)(bias + col);
            int rg = m0 + wm * 32 + am * 16 + trow;
            float x0 = acc[am][bn][0] + bv.x, y0 = acc[am][bn][1] + bv.y;
            float x1 = acc[am][bn][2] + bv.x, y1 = acc[am][bn][3] + bv.y;
            if (HALF_OUT) {
                *(__half2*)(Ch + (size_t)rg * N + col)       = __floats2half2_rn(x0, y0);
                *(__half2*)(Ch + (size_t)(rg + 8) * N + col) = __floats2half2_rn(x1, y1);
            } else {
                float2 o0 = {x0, y0}, o1 = {x1, y1};
                *(float2*)(Cf + (size_t)rg * N + col)       = o0;
                *(float2*)(Cf + (size_t)(rg + 8) * N + col) = o1;
            }
        }
    }
}

// ---------------------------------------------------------------------------
// Tensor-core flash attention, fp16 in/out, fp32 accumulate.
// CTA = 128 queries of one (b,h); 8 warps x 16 rows; key blocks of 64.
// 3-stage cp.async KV pipeline, one sync per block. grid: (bh, mtile rev).
// ---------------------------------------------------------------------------
#define QSTR 72
#define KVSTG 18432   // bytes per KV stage (K 64x72 + V 64x72 halves)

__global__ __launch_bounds__(256) void attn_mma_kernel(
    const __half* __restrict__ qkv, __half* __restrict__ outa)
{
    extern __shared__ char dsma[];
    __half (*Qs)[QSTR] = (__half(*)[QSTR])dsma;
    char* kvb = dsma + 128 * QSTR * 2;   // 18432

    const int tid  = threadIdx.x;
    const int lane = tid & 31;
    const int wid  = tid >> 5;
    const int bh = blockIdx.x;
    const int b  = bh >> 4;
    const int h  = bh & 15;
    const int m0 = (int)(gridDim.y - 1 - blockIdx.y) << 7;  // longest first
    const int qrow0 = wid << 4;

    // Load Q tile (fp16 direct)
    const __half* qb = qkv + ((size_t)(b * T_SEQ + m0)) * C3 + h * HD;
    for (int i = tid; i < 1024; i += 256) {
        int r = i >> 3, c = (i & 7) << 3;
        *(uint4*)&Qs[r][c] = *(const uint4*)(qb + (size_t)r * C3 + c);
    }

    auto load_stage = [&](int s, int n0) {
        const __half* kp = qkv + ((size_t)(b * T_SEQ + n0)) * C3 + DM + h * HD;
        const __half* vp = kp + DM;
        char* base = kvb + s * KVSTG;
        for (int i = tid; i < 1024; i += 256) {
            int isV = i >> 9;
            int j = i & 511;
            int r = j >> 3, c = (j & 7) << 3;
            const __half* src = (isV ? vp : kp) + (size_t)r * C3 + c;
            cp_async16(cvta_s(base + isV * 9216 + r * (QSTR * 2) + c * 2), src);
        }
        asm volatile("cp.async.commit_group;" ::: "memory");
    };

    float m_[2] = {-1e30f, -1e30f};
    float l_[2] = {0.f, 0.f};
    float o[8][4];
#pragma unroll
    for (int j = 0; j < 8; j++)
#pragma unroll
        for (int k = 0; k < 4; k++) o[j][k] = 0.f;

    const int rA = m0 + qrow0 + (lane >> 2);
    const int rB = rA + 8;

    const int nkb = (m0 >> 6) + 2;
    load_stage(0, 0);
    load_stage(1, 64);

    for (int kb = 0; kb < nkb; kb++) {
        if (kb + 1 < nkb) asm volatile("cp.async.wait_group 1;" ::: "memory");
        else              asm volatile("cp.async.wait_group 0;" ::: "memory");
        __syncthreads();
        if (kb + 2 < nkb) load_stage((kb + 2) % 3, (kb + 2) << 6);

        const int n0 = kb << 6;
        __half (*Ks)[QSTR] = (__half(*)[QSTR])(kvb + (kb % 3) * KVSTG);
        __half (*Vs)[QSTR] = (__half(*)[QSTR])(kvb + (kb % 3) * KVSTG + 9216);

        if (m0 + qrow0 + 15 < n0) continue;   // fully masked warp tile

        // S = Q @ K^T
        float s_[8][4];
#pragma unroll
        for (int j = 0; j < 8; j++)
#pragma unroll
            for (int k = 0; k < 4; k++) s_[j][k] = 0.f;

#pragma unroll
        for (int ks = 0; ks < 64; ks += 16) {
            uint32_t a[4];
            ldmx4(a, cvta_s(&Qs[qrow0 + (lane & 15)][ks + ((lane >> 4) << 3)]));
#pragma unroll
            for (int j = 0; j < 4; j++) {
                uint32_t bf[4];
                ldmx4(bf, cvta_s(&Ks[j * 16 + (lane & 7) + ((lane >> 4) << 3)]
                                    [ks + (((lane >> 3) & 1) << 3)]));
                mma_f16(s_[2 * j],     a, bf[0], bf[1]);
                mma_f16(s_[2 * j + 1], a, bf[2], bf[3]);
            }
        }

        // scale + causal mask
#pragma unroll
        for (int j = 0; j < 8; j++) {
            int cg = n0 + j * 8 + ((lane & 3) << 1);
            s_[j][0] = (cg     <= rA) ? s_[j][0] * 0.125f : -1e30f;
            s_[j][1] = (cg + 1 <= rA) ? s_[j][1] * 0.125f : -1e30f;
            s_[j][2] = (cg     <= rB) ? s_[j][2] * 0.125f : -1e30f;
            s_[j][3] = (cg + 1 <= rB) ? s_[j][3] * 0.125f : -1e30f;
        }

        // online softmax (rows rA, rB), quad-lane reduction
        float mxA = -1e30f, mxB = -1e30f;
#pragma unroll
        for (int j = 0; j < 8; j++) {
            mxA = fmaxf(mxA, fmaxf(s_[j][0], s_[j][1]));
            mxB = fmaxf(mxB, fmaxf(s_[j][2], s_[j][3]));
        }
        mxA = fmaxf(mxA, __shfl_xor_sync(0xffffffffu, mxA, 1));
        mxA = fmaxf(mxA, __shfl_xor_sync(0xffffffffu, mxA, 2));
        mxB = fmaxf(mxB, __shfl_xor_sync(0xffffffffu, mxB, 1));
        mxB = fmaxf(mxB, __shfl_xor_sync(0xffffffffu, mxB, 2));

        float mnA = fmaxf(m_[0], mxA), mnB = fmaxf(m_[1], mxB);
        float cA = __expf(m_[0] - mnA), cB = __expf(m_[1] - mnB);
        m_[0] = mnA; m_[1] = mnB;

        float sumA = 0.f, sumB = 0.f;
#pragma unroll
        for (int j = 0; j < 8; j++) {
            s_[j][0] = __expf(s_[j][0] - mnA);
            s_[j][1] = __expf(s_[j][1] - mnA);
            s_[j][2] = __expf(s_[j][2] - mnB);
            s_[j][3] = __expf(s_[j][3] - mnB);
            sumA += s_[j][0] + s_[j][1];
            sumB += s_[j][2] + s_[j][3];
        }
        sumA += __shfl_xor_sync(0xffffffffu, sumA, 1);
        sumA += __shfl_xor_sync(0xffffffffu, sumA, 2);
        sumB += __shfl_xor_sync(0xffffffffu, sumB, 1);
        sumB += __shfl_xor_sync(0xffffffffu, sumB, 2);
        l_[0] = l_[0] * cA + sumA;
        l_[1] = l_[1] * cB + sumB;

#pragma unroll
        for (int j = 0; j < 8; j++) {
            o[j][0] *= cA; o[j][1] *= cA;
            o[j][2] *= cB; o[j][3] *= cB;
        }

        // O += P @ V
#pragma unroll
        for (int t = 0; t < 4; t++) {
            uint32_t aP[4];
            aP[0] = pack_h2(s_[2 * t][0],     s_[2 * t][1]);
            aP[1] = pack_h2(s_[2 * t][2],     s_[2 * t][3]);
            aP[2] = pack_h2(s_[2 * t + 1][0], s_[2 * t + 1][1]);
            aP[3] = pack_h2(s_[2 * t + 1][2], s_[2 * t + 1][3]);
#pragma unroll
            for (int jd = 0; jd < 4; jd++) {
                uint32_t bf[4];
                ldmx4_trans(bf, cvta_s(&Vs[t * 16 + (((lane >> 3) & 1) << 3) + (lane & 7)]
                                          [jd * 16 + ((lane >> 4) << 3)]));
                mma_f16(o[2 * jd],     aP, bf[0], bf[1]);
                mma_f16(o[2 * jd + 1], aP, bf[2], bf[3]);
            }
        }
    }

    // epilogue: normalize, write fp16 [B*T, 1024] at head offset
    float invA = 1.f / l_[0], invB = 1.f / l_[1];
    __half* oA = outa + ((size_t)(b * T_SEQ) + rA) * DM + h * HD;
    __half* oB = outa + ((size_t)(b * T_SEQ) + rB) * DM + h * HD;
#pragma unroll
    for (int j = 0; j < 8; j++) {
        int col = j * 8 + ((lane & 3) << 1);
        *(__half2*)(oA + col) = __floats2half2_rn(o[j][0] * invA, o[j][1] * invA);
        *(__half2*)(oB + col) = __floats2half2_rn(o[j][2] * invB, o[j][3] * invB);
    }
}

// ---------------------------------------------------------------------------
extern "C" void kernel_launch(void* const* d_in, const int* in_sizes, int n_in,
                              void* d_out, int out_size)
{
    const float* x      = (const float*)d_in[0];
    const float* w_qkv  = (const float*)d_in[1];
    const float* b_qkv  = (const float*)d_in[2];
    const float* w_proj = (const float*)d_in[3];
    const float* b_proj = (const float*)d_in[4];
    float* out = (float*)d_out;

    __half *xh, *qkvh, *atth, *wqh, *wph;
    cudaGetSymbolAddress((void**)&xh, g_xh);
    cudaGetSymbolAddress((void**)&qkvh, g_qkvh);
    cudaGetSymbolAddress((void**)&atth, g_atth);
    cudaGetSymbolAddress((void**)&wqh, g_wqh);
    cudaGetSymbolAddress((void**)&wph, g_wph);

    const int smem_gemm = 3 * 2 * 128 * ASTR * (int)sizeof(__half);  // 61440
    cudaFuncSetAttribute(gemm_mma_kernel<true>,
                         cudaFuncAttributeMaxDynamicSharedMemorySize, smem_gemm);
    cudaFuncSetAttribute(gemm_mma_kernel<false>,
                         cudaFuncAttributeMaxDynamicSharedMemorySize, smem_gemm);
    const int smem_attn = 128 * QSTR * 2 + 3 * KVSTG;  // 73728
    cudaFuncSetAttribute(attn_mma_kernel,
                         cudaFuncAttributeMaxDynamicSharedMemorySize, smem_attn);

    // 1) x -> fp16
    convh_kernel<<<4096, 256>>>(x, xh);
    // 2) w_qkv -> transposed fp16 [3072,1024]
    tconvh_kernel<<<dim3(96, 32), 256>>>(w_qkv, wqh, 3072);
    // 3) QKV GEMM (fp16 out, bias fused)
    gemm_mma_kernel<true><<<dim3(24, 32), 256, smem_gemm>>>(
        xh, wqh, b_qkv, nullptr, qkvh, 4096, 3072);
    // 4) causal flash attention (fp16 in/out)
    attn_mma_kernel<<<dim3(2 * NH, T_SEQ / 128), 256, smem_attn>>>(qkvh, atth);
    // 5) w_proj -> transposed fp16 [1024,1024]
    tconvh_kernel<<<dim3(32, 32), 256>>>(w_proj, wph, 1024);
    // 6) proj GEMM (fp32 out, bias fused)
    gemm_mma_kernel<false><<<dim3(8, 32), 256, smem_gemm>>>(
        atth, wph, b_proj, out, nullptr, 4096, 1024);
}